// round 4
// baseline (speedup 1.0000x reference)
#include <cuda_runtime.h>
#include <mma.h>
#include <math.h>
#include <stdint.h>

using namespace nvcuda;

#define BATCH   4096
#define DDIM    1024
#define NKB     65536
#define NSPLIT  8
#define KBSPLIT (NKB / NSPLIT)
#define TOPK    32
#define OUTW    3072

// ---------------- scratch (static device globals; no allocations) ----------
__device__ float g_q[BATCH * DDIM];             // q = C @ Q^T (fp32)
__device__ float g_qsq[BATCH];                  // ||q_i||^2
__device__ float g_kbsq[NKB];                   // ||kb_j||^2
__device__ float g_pd[BATCH * NSPLIT * TOPK];   // partial top-k d2
__device__ int   g_pi[BATCH * NSPLIT * TOPK];   // partial top-k indices

__device__ __forceinline__ float f_inf() { return __int_as_float(0x7f800000); }

// Stage a 128x32 fp32 tile into shared as tf32, row stride 36 (pad for banks).
__device__ __forceinline__ void stage128x32(float* dst, const float* __restrict__ src,
                                            int row_base, int kk, int tid) {
#pragma unroll
    for (int i = 0; i < 4; i++) {
        int e   = tid + i * 256;   // 1024 float4 slots
        int row = e >> 3;          // 8 float4 per row
        int c4  = e & 7;
        float4 v = *reinterpret_cast<const float4*>(
            src + (size_t)(row_base + row) * DDIM + kk + c4 * 4);
        float4 w;
        w.x = wmma::__float_to_tf32(v.x);
        w.y = wmma::__float_to_tf32(v.y);
        w.z = wmma::__float_to_tf32(v.z);
        w.w = wmma::__float_to_tf32(v.w);
        *reinterpret_cast<float4*>(dst + row * 36 + c4 * 4) = w;
    }
}

// ---------------- K1: q = C @ Q^T  (tf32 wmma, 128x128 tiles) ---------------
__global__ __launch_bounds__(256) void qgemm_kernel(const float* __restrict__ Cm,
                                                    const float* __restrict__ Qw) {
    extern __shared__ float sm[];
    float* As = sm;                 // 128x36
    float* Bs = sm + 128 * 36;      // 128x36
    int tid  = threadIdx.x;
    int warp = tid >> 5, wm = warp >> 1, wn = warp & 1;
    int mbase = blockIdx.y * 128;
    int nbase = blockIdx.x * 128;

    wmma::fragment<wmma::accumulator, 16, 16, 8, float> fc[2][4];
#pragma unroll
    for (int i = 0; i < 2; i++)
#pragma unroll
        for (int j = 0; j < 4; j++) wmma::fill_fragment(fc[i][j], 0.0f);

    for (int kk = 0; kk < DDIM; kk += 32) {
        stage128x32(As, Cm, mbase, kk, tid);
        stage128x32(Bs, Qw, nbase, kk, tid);
        __syncthreads();
#pragma unroll
        for (int ks = 0; ks < 4; ks++) {
            wmma::fragment<wmma::matrix_a, 16, 16, 8, wmma::precision::tf32, wmma::row_major> fa0, fa1;
            wmma::load_matrix_sync(fa0, As + (wm * 32) * 36 + ks * 8, 36);
            wmma::load_matrix_sync(fa1, As + (wm * 32 + 16) * 36 + ks * 8, 36);
#pragma unroll
            for (int j = 0; j < 4; j++) {
                wmma::fragment<wmma::matrix_b, 16, 16, 8, wmma::precision::tf32, wmma::col_major> fb;
                wmma::load_matrix_sync(fb, Bs + (wn * 64 + j * 16) * 36 + ks * 8, 36);
                wmma::mma_sync(fc[0][j], fa0, fb, fc[0][j]);
                wmma::mma_sync(fc[1][j], fa1, fb, fc[1][j]);
            }
        }
        __syncthreads();
    }
#pragma unroll
    for (int i = 0; i < 2; i++)
#pragma unroll
        for (int j = 0; j < 4; j++) {
            float* dst = g_q + (size_t)(mbase + wm * 32 + i * 16) * DDIM
                             + nbase + wn * 64 + j * 16;
            wmma::store_matrix_sync(dst, fc[i][j], DDIM, wmma::mem_row_major);
        }
}

// ---------------- K2: row sums of squares (q and kb) ------------------------
__global__ __launch_bounds__(256) void rowsq_kernel(const float* __restrict__ kb) {
    int warp = threadIdx.x >> 5, lane = threadIdx.x & 31;
    int row = blockIdx.x * 8 + warp;
    const float* src;
    float* dst;
    if (row < BATCH) {
        src = g_q + (size_t)row * DDIM;
        dst = &g_qsq[row];
    } else {
        int r2 = row - BATCH;
        if (r2 >= NKB) return;
        src = kb + (size_t)r2 * DDIM;
        dst = &g_kbsq[r2];
    }
    const float4* p = reinterpret_cast<const float4*>(src);
    float s = 0.f;
#pragma unroll
    for (int i = 0; i < 8; i++) {
        float4 v = p[lane + i * 32];
        s += v.x * v.x + v.y * v.y + v.z * v.z + v.w * v.w;
    }
#pragma unroll
    for (int o = 16; o; o >>= 1) s += __shfl_xor_sync(0xffffffffu, s, o);
    if (lane == 0) *dst = s;
}

// ---------------- K3: fused distance GEMM + streaming top-32 ----------------
// grid: (BATCH/128 q-tiles, NSPLIT kb-splits). Each CTA: 128 queries vs 8192 kb rows.
__global__ __launch_bounds__(256) void dist_topk_kernel(const float* __restrict__ kb) {
    extern __shared__ float sm[];
    float* As   = sm;                      // 128x36
    float* Bs   = As + 128 * 36;           // 128x36
    float* Ds   = Bs + 128 * 36;           // 128x132 dot tile
    float* skb  = Ds + 128 * 132;          // 128 kb_sq
    float* topd = skb + 128;               // 128x33
    int*   topi = (int*)(topd + 128 * 33); // 128x33

    int tid  = threadIdx.x;
    int warp = tid >> 5, wm = warp >> 1, wn = warp & 1;
    int mbase = blockIdx.x * 128;
    int split = blockIdx.y;

    float qs = 0.f;
    float rmax = f_inf();
    int   rpos = 0;
    if (tid < 128) {
        qs = g_qsq[mbase + tid];
#pragma unroll
        for (int k = 0; k < TOPK; k++) topd[tid * 33 + k] = f_inf();
    }

    for (int nt = 0; nt < KBSPLIT / 128; nt++) {
        int nbase = split * KBSPLIT + nt * 128;

        wmma::fragment<wmma::accumulator, 16, 16, 8, float> fc[2][4];
#pragma unroll
        for (int i = 0; i < 2; i++)
#pragma unroll
            for (int j = 0; j < 4; j++) wmma::fill_fragment(fc[i][j], 0.0f);

        for (int kk = 0; kk < DDIM; kk += 32) {
            stage128x32(As, g_q, mbase, kk, tid);
            stage128x32(Bs, kb, nbase, kk, tid);
            __syncthreads();
#pragma unroll
            for (int ks = 0; ks < 4; ks++) {
                wmma::fragment<wmma::matrix_a, 16, 16, 8, wmma::precision::tf32, wmma::row_major> fa0, fa1;
                wmma::load_matrix_sync(fa0, As + (wm * 32) * 36 + ks * 8, 36);
                wmma::load_matrix_sync(fa1, As + (wm * 32 + 16) * 36 + ks * 8, 36);
#pragma unroll
                for (int j = 0; j < 4; j++) {
                    wmma::fragment<wmma::matrix_b, 16, 16, 8, wmma::precision::tf32, wmma::col_major> fb;
                    wmma::load_matrix_sync(fb, Bs + (wn * 64 + j * 16) * 36 + ks * 8, 36);
                    wmma::mma_sync(fc[0][j], fa0, fb, fc[0][j]);
                    wmma::mma_sync(fc[1][j], fa1, fb, fc[1][j]);
                }
            }
            __syncthreads();
        }

        // dot tile -> shared
#pragma unroll
        for (int i = 0; i < 2; i++)
#pragma unroll
            for (int j = 0; j < 4; j++)
                wmma::store_matrix_sync(Ds + (wm * 32 + i * 16) * 132 + wn * 64 + j * 16,
                                        fc[i][j], 132, wmma::mem_row_major);
        if (tid < 128) skb[tid] = g_kbsq[nbase + tid];
        __syncthreads();

        // per-row threshold-filtered top-32 insertion (1 thread per query row)
        if (tid < 128) {
            float* myd = topd + tid * 33;
            int*   myi = topi + tid * 33;
            const float* drow = Ds + tid * 132;
            for (int j = 0; j < 128; j++) {
                float d2 = qs + skb[j] - 2.0f * drow[j];
                if (d2 < rmax) {
                    myd[rpos] = d2;
                    myi[rpos] = nbase + j;
                    float m = -3.4e38f;
                    int p = 0;
#pragma unroll
                    for (int k = 0; k < TOPK; k++) {
                        float v = myd[k];
                        if (v > m) { m = v; p = k; }
                    }
                    rmax = m;
                    rpos = p;
                }
            }
        }
        __syncthreads();
    }

    if (tid < 128) {
#pragma unroll
        for (int k = 0; k < TOPK; k++) {
            size_t o = ((size_t)(mbase + tid) * NSPLIT + split) * TOPK + k;
            g_pd[o] = topd[tid * 33 + k];
            g_pi[o] = topi[tid * 33 + k];
        }
    }
}

// ---------------- K4: merge splits, softmax, gather, SiLU epilogue ----------
__device__ __forceinline__ float silu_f(float x) { return x / (1.0f + expf(-x)); }

__global__ __launch_bounds__(256) void merge_kernel(const float* __restrict__ kb,
                                                    const float* __restrict__ Cm,
                                                    const float* __restrict__ Km,
                                                    const float* __restrict__ temp_p,
                                                    float* __restrict__ out) {
    __shared__ float cd[256];
    __shared__ int   ci[256];
    __shared__ float sv[256];
    __shared__ int   sp[256];
    __shared__ float sd[TOPK];
    __shared__ int   si[TOPK];
    __shared__ float sw[TOPK];

    int q = blockIdx.x;
    int tid = threadIdx.x;

    cd[tid] = g_pd[(size_t)q * NSPLIT * TOPK + tid];
    ci[tid] = g_pi[(size_t)q * NSPLIT * TOPK + tid];
    __syncthreads();

    // select 32 smallest of 256 candidates via repeated argmin
    for (int s = 0; s < TOPK; s++) {
        sv[tid] = cd[tid];
        sp[tid] = tid;
        __syncthreads();
#pragma unroll
        for (int off = 128; off; off >>= 1) {
            if (tid < off && sv[tid + off] < sv[tid]) {
                sv[tid] = sv[tid + off];
                sp[tid] = sp[tid + off];
            }
            __syncthreads();
        }
        if (tid == 0) {
            int p = sp[0];
            sd[s] = cd[p];
            si[s] = ci[p];
            cd[p] = f_inf();
        }
        __syncthreads();
    }

    // softmax(-dist / temperature) over the 32 selected
    if (tid < TOPK) {
        float dist  = sqrtf(fmaxf(sd[tid], 0.0f));
        float logit = -dist / temp_p[0];
        float m = logit;
#pragma unroll
        for (int o = 16; o; o >>= 1) m = fmaxf(m, __shfl_xor_sync(0xffffffffu, m, o));
        float e = expf(logit - m);
        float ss = e;
#pragma unroll
        for (int o = 16; o; o >>= 1) ss += __shfl_xor_sync(0xffffffffu, ss, o);
        sw[tid] = e / ss;
    }
    __syncthreads();

    // T = sum_k w_k * kb[idx_k]  (each thread owns 4 contiguous cols)
    float4 acc = make_float4(0.f, 0.f, 0.f, 0.f);
#pragma unroll 4
    for (int k = 0; k < TOPK; k++) {
        float wk = sw[k];
        const float4* row = reinterpret_cast<const float4*>(kb + (size_t)si[k] * DDIM);
        float4 v = row[tid];
        acc.x += wk * v.x; acc.y += wk * v.y; acc.z += wk * v.z; acc.w += wk * v.w;
    }

    float4* o4 = reinterpret_cast<float4*>(out + (size_t)q * OUTW);
    const float4* c4 = reinterpret_cast<const float4*>(Cm + (size_t)q * DDIM);
    const float4* k4 = reinterpret_cast<const float4*>(Km + (size_t)q * DDIM);

    float4 cv = c4[tid], kv = k4[tid], r;
    r.x = silu_f(cv.x); r.y = silu_f(cv.y); r.z = silu_f(cv.z); r.w = silu_f(cv.w);
    o4[tid] = r;
    r.x = silu_f(0.5f * kv.x); r.y = silu_f(0.5f * kv.y);
    r.z = silu_f(0.5f * kv.z); r.w = silu_f(0.5f * kv.w);
    o4[256 + tid] = r;
    r.x = silu_f(0.25f * acc.x); r.y = silu_f(0.25f * acc.y);
    r.z = silu_f(0.25f * acc.z); r.w = silu_f(0.25f * acc.w);
    o4[512 + tid] = r;
}

// ---------------- launch -----------------------------------------------------
extern "C" void kernel_launch(void* const* d_in, const int* in_sizes, int n_in,
                              void* d_out, int out_size) {
    // size-based routing (C and K share a size -> order preserved)
    int iC = -1, iK = -1, iKB = -1, iQ = -1, iT = -1;
    for (int i = 0; i < n_in; i++) {
        int s = in_sizes[i];
        if (s == NKB * DDIM)            iKB = i;
        else if (s == DDIM * DDIM)      iQ = i;
        else if (s == BATCH * DDIM)     { if (iC < 0) iC = i; else iK = i; }
        else if (s == 1)                { if (iT < 0) iT = i; }
    }
    const float* C    = (const float*)d_in[iC];
    const float* Kin  = (const float*)d_in[iK];
    const float* kb   = (const float*)d_in[iKB];
    const float* Qw   = (const float*)d_in[iQ];
    const float* temp = (const float*)d_in[iT];
    float* out = (float*)d_out;

    const int k3_smem = (128 * 36 * 2 + 128 * 132 + 128 + 128 * 33) * 4 + 128 * 33 * 4;
    cudaFuncSetAttribute(dist_topk_kernel,
                         cudaFuncAttributeMaxDynamicSharedMemorySize, k3_smem);

    qgemm_kernel<<<dim3(DDIM / 128, BATCH / 128), 256, 2 * 128 * 36 * 4>>>(C, Qw);
    rowsq_kernel<<<(BATCH + NKB) / 8, 256>>>(kb);
    dist_topk_kernel<<<dim3(BATCH / 128, NSPLIT), 256, k3_smem>>>(kb);
    merge_kernel<<<BATCH, 256>>>(kb, C, Kin, temp, out);
}

// round 7
// speedup vs baseline: 1.0930x; 1.0930x over previous
#include <cuda_runtime.h>
#include <mma.h>
#include <math.h>
#include <stdint.h>

using namespace nvcuda;

#define BATCH   4096
#define DDIM    1024
#define NKB     65536
#define NSPLIT  4
#define KBSPLIT (NKB / NSPLIT)      // 16384
#define TOPK    32
#define OUTW    3072
#define TILE_N  128
#define TILES   (KBSPLIT / TILE_N)  // 128 tiles per CTA
#define NCHUNK  (TILES * 32)        // flat (tile,chunk) count
#define NLIST   (NSPLIT * 2)        // 8 partial top-k lists per query
#define NCAND   (NLIST * TOPK)      // 256 candidates per query
#define RESCORE 64                  // exact-rescore margin

// ---- K3 shared memory layout (bytes) ----
#define STG_BYTES 36864             // one stage: A 128x36 fl + B 128x36 fl
#define OFF_D     73728             // Ds 128x132 fp32
#define OFF_KQ    141312            // 128 kb_sq
#define K3_SMEM   141824

// ---------------- scratch (static device globals) ----------------
__device__ float g_q[BATCH * DDIM];
__device__ float g_kbsq[NKB];
__device__ float g_pd[BATCH * NCAND];
__device__ int   g_pi[BATCH * NCAND];

__device__ __forceinline__ float f_inf() { return __int_as_float(0x7f800000); }

__device__ __forceinline__ uint32_t smem_u32(const void* p) {
    uint32_t a;
    asm("{ .reg .u64 t; cvta.to.shared.u64 t, %1; cvt.u32.u64 %0, t; }" : "=r"(a) : "l"(p));
    return a;
}
__device__ __forceinline__ void cp16(uint32_t dst, const void* src) {
    asm volatile("cp.async.cg.shared.global [%0], [%1], 16;" :: "r"(dst), "l"(src));
}
#define CP_COMMIT() asm volatile("cp.async.commit_group;" ::: "memory")
#define CP_WAIT0()  asm volatile("cp.async.wait_group 0;"  ::: "memory")

// ---------------- K1: q = C @ Q^T, exact fp32 SIMT (128x128 tiles) ----------
__global__ __launch_bounds__(256) void qgemm_fp32(const float* __restrict__ Cm,
                                                  const float* __restrict__ Qw) {
    __shared__ float At[8][132];   // transposed: At[k][m]
    __shared__ float Bt[8][132];   // transposed: Bt[k][n]
    const int tid = threadIdx.x;
    const int mbase = blockIdx.y * 128, nbase = blockIdx.x * 128;
    const int tr = tid >> 4, tc = tid & 15;     // 16x16 thread grid, 8x8 micro-tile
    const int lr = tid >> 1, lc = (tid & 1) * 4;

    float acc[8][8];
#pragma unroll
    for (int i = 0; i < 8; i++)
#pragma unroll
        for (int j = 0; j < 8; j++) acc[i][j] = 0.f;

    for (int kk = 0; kk < DDIM; kk += 8) {
        float4 av = *reinterpret_cast<const float4*>(Cm + (size_t)(mbase + lr) * DDIM + kk + lc);
        float4 bv = *reinterpret_cast<const float4*>(Qw + (size_t)(nbase + lr) * DDIM + kk + lc);
        __syncthreads();
        At[lc + 0][lr] = av.x; At[lc + 1][lr] = av.y; At[lc + 2][lr] = av.z; At[lc + 3][lr] = av.w;
        Bt[lc + 0][lr] = bv.x; Bt[lc + 1][lr] = bv.y; Bt[lc + 2][lr] = bv.z; Bt[lc + 3][lr] = bv.w;
        __syncthreads();
#pragma unroll
        for (int k = 0; k < 8; k++) {
            float4 a0 = *reinterpret_cast<float4*>(&At[k][tr * 8]);
            float4 a1 = *reinterpret_cast<float4*>(&At[k][tr * 8 + 4]);
            float4 b0 = *reinterpret_cast<float4*>(&Bt[k][tc * 8]);
            float4 b1 = *reinterpret_cast<float4*>(&Bt[k][tc * 8 + 4]);
            float a[8] = {a0.x, a0.y, a0.z, a0.w, a1.x, a1.y, a1.z, a1.w};
            float b[8] = {b0.x, b0.y, b0.z, b0.w, b1.x, b1.y, b1.z, b1.w};
#pragma unroll
            for (int i = 0; i < 8; i++)
#pragma unroll
                for (int j = 0; j < 8; j++) acc[i][j] += a[i] * b[j];
        }
    }
#pragma unroll
    for (int i = 0; i < 8; i++) {
        float* dst = g_q + (size_t)(mbase + tr * 8 + i) * DDIM + nbase + tc * 8;
#pragma unroll
        for (int j = 0; j < 8; j += 4)
            *reinterpret_cast<float4*>(dst + j) =
                make_float4(acc[i][j], acc[i][j + 1], acc[i][j + 2], acc[i][j + 3]);
    }
}

// ---------------- K2: kb row sums of squares ----------------
__global__ __launch_bounds__(256) void rowsq_kernel(const float* __restrict__ kb) {
    int warp = threadIdx.x >> 5, lane = threadIdx.x & 31;
    int row = blockIdx.x * 8 + warp;
    if (row >= NKB) return;
    const float4* p = reinterpret_cast<const float4*>(kb + (size_t)row * DDIM);
    float s = 0.f;
#pragma unroll
    for (int i = 0; i < 8; i++) {
        float4 v = p[lane + i * 32];
        s += v.x * v.x + v.y * v.y + v.z * v.z + v.w * v.w;
    }
#pragma unroll
    for (int o = 16; o; o >>= 1) s += __shfl_xor_sync(0xffffffffu, s, o);
    if (lane == 0) g_kbsq[row] = s;
}

// ---------------- K3: cp.async pipelined tf32 MMA + streaming top-32 --------
__device__ __forceinline__ void k3_issue(uint32_t sb, int tid, int mbase, int split,
                                         int g, const float* __restrict__ kb) {
    const int t = g >> 5, s = g & 31, stage = g & 1;
    const int kk = s * 32;
    const int nbase = split * KBSPLIT + t * TILE_N;
    const uint32_t sA = sb + stage * STG_BYTES;
    const uint32_t sB = sA + 18432;
#pragma unroll
    for (int i = 0; i < 4; i++) {
        int e = tid + i * 256, r = e >> 3, c4 = e & 7;
        cp16(sA + (uint32_t)((r * 36 + c4 * 4) << 2),
             g_q + (size_t)(mbase + r) * DDIM + kk + c4 * 4);
    }
#pragma unroll
    for (int i = 0; i < 4; i++) {
        int e = tid + i * 256, r = e >> 3, c4 = e & 7;
        cp16(sB + (uint32_t)((r * 36 + c4 * 4) << 2),
             kb + (size_t)(nbase + r) * DDIM + kk + c4 * 4);
    }
    CP_COMMIT();
}

__global__ __launch_bounds__(256, 1) void dist_topk_cp(const float* __restrict__ kb) {
    extern __shared__ char smem[];
    const uint32_t sb = smem_u32(smem);
    float* Ds     = reinterpret_cast<float*>(smem + OFF_D);
    float* s_kbsq = reinterpret_cast<float*>(smem + OFF_KQ);
    const int tid  = threadIdx.x;
    const int warp = tid >> 5, wm = warp >> 1, wn = warp & 1;
    const int mbase = blockIdx.x * 128;
    const int split = blockIdx.y;
    const int row = tid & 127, half = tid >> 7;

    float td[TOPK];
    int   ti[TOPK];
#pragma unroll
    for (int k = 0; k < TOPK; k++) { td[k] = f_inf(); ti[k] = 0; }
    float rmax = f_inf();
    int   rpos = 0;

    wmma::fragment<wmma::accumulator, 16, 16, 8, float> fc[2][4];
#pragma unroll
    for (int i = 0; i < 2; i++)
#pragma unroll
        for (int j = 0; j < 4; j++) wmma::fill_fragment(fc[i][j], 0.0f);

    k3_issue(sb, tid, mbase, split, 0, kb);

    for (int g = 0; g < NCHUNK; g++) {
        CP_WAIT0();
        __syncthreads();
        if (g + 1 < NCHUNK) k3_issue(sb, tid, mbase, split, g + 1, kb);

        {
            float* As = reinterpret_cast<float*>(smem + (g & 1) * STG_BYTES);
            float* Bs = As + 4608;
#pragma unroll
            for (int ks = 0; ks < 4; ks++) {
                wmma::fragment<wmma::matrix_a, 16, 16, 8, wmma::precision::tf32, wmma::row_major> fa0, fa1;
                wmma::load_matrix_sync(fa0, As + (wm * 32) * 36 + ks * 8, 36);
                wmma::load_matrix_sync(fa1, As + (wm * 32 + 16) * 36 + ks * 8, 36);
#pragma unroll
                for (int j = 0; j < 4; j++) {
                    wmma::fragment<wmma::matrix_b, 16, 16, 8, wmma::precision::tf32, wmma::col_major> fb;
                    wmma::load_matrix_sync(fb, Bs + (wn * 64 + j * 16) * 36 + ks * 8, 36);
                    wmma::mma_sync(fc[0][j], fa0, fb, fc[0][j]);
                    wmma::mma_sync(fc[1][j], fa1, fb, fc[1][j]);
                }
            }
        }

        if ((g & 31) == 31) {
            const int t = g >> 5;
            const int nbase = split * KBSPLIT + t * TILE_N;
#pragma unroll
            for (int i = 0; i < 2; i++)
#pragma unroll
                for (int j = 0; j < 4; j++)
                    wmma::store_matrix_sync(Ds + (wm * 32 + i * 16) * 132 + wn * 64 + j * 16,
                                            fc[i][j], 132, wmma::mem_row_major);
            if (tid < 128) s_kbsq[tid] = g_kbsq[nbase + tid];
            __syncthreads();

            const float* drow = Ds + row * 132 + half * 64;
            const float* kq   = s_kbsq + half * 64;
            const int ibase   = nbase + half * 64;
#pragma unroll 4
            for (int j = 0; j < 64; j++) {
                float sc = kq[j] - 2.0f * drow[j];
                if (sc < rmax) {
                    int idx = ibase + j;
#pragma unroll
                    for (int k = 0; k < TOPK; k++)
                        if (k == rpos) { td[k] = sc; ti[k] = idx; }
                    float nm = -3.4e38f;
                    int np = 0;
#pragma unroll
                    for (int k = 0; k < TOPK; k++)
                        if (td[k] > nm) { nm = td[k]; np = k; }
                    rmax = nm; rpos = np;
                }
            }
            __syncthreads();
#pragma unroll
            for (int i = 0; i < 2; i++)
#pragma unroll
                for (int j = 0; j < 4; j++) wmma::fill_fragment(fc[i][j], 0.0f);
        }
    }

    const int list = split * 2 + half;
#pragma unroll
    for (int k = 0; k < TOPK; k++) {
        size_t o = ((size_t)(mbase + row) * NLIST + list) * TOPK + k;
        g_pd[o] = td[k];
        g_pi[o] = ti[k];
    }
}

// ---------------- K4: approx top-64 -> exact rescoring -> top-32 -> SiLU ----
__device__ __forceinline__ float silu_f(float x) { return x / (1.0f + expf(-x)); }

__global__ __launch_bounds__(256) void finalize_kernel(const float* __restrict__ kb,
                                                       const float* __restrict__ Cm,
                                                       const float* __restrict__ Km,
                                                       const float* __restrict__ temp_p,
                                                       float* __restrict__ out) {
    __shared__ float qrow[DDIM];
    __shared__ float cd[NCAND];
    __shared__ int   ci[NCAND];
    __shared__ int   slot64[RESCORE];
    __shared__ float ed[RESCORE];
    __shared__ int   ei[RESCORE];
    __shared__ float sd[TOPK];
    __shared__ int   si[TOPK];
    __shared__ float wts[TOPK];

    const int q = blockIdx.x, tid = threadIdx.x, wid = tid >> 5, lane = tid & 31;

    cd[tid] = g_pd[(size_t)q * NCAND + tid];
    ci[tid] = g_pi[(size_t)q * NCAND + tid];
    reinterpret_cast<float4*>(qrow)[tid] =
        reinterpret_cast<const float4*>(g_q + (size_t)q * DDIM)[tid];
    __syncthreads();

    // rank each candidate among the 256 approx scores (index tiebreak)
    {
        float mine = cd[tid];
        int r = 0;
#pragma unroll 8
        for (int j = 0; j < NCAND; j++) {
            float v = cd[j];
            r += (v < mine) || (v == mine && j < tid);
        }
        if (r < RESCORE) slot64[r] = tid;
    }
    __syncthreads();

    // exact fp32 d2 for the top-64 approx candidates (warp w: rows w*8..w*8+7)
#pragma unroll 1
    for (int r8 = 0; r8 < RESCORE / 8; r8++) {
        const int k = wid * (RESCORE / 8) + r8;
        const int kbrow = ci[slot64[k]];
        const float4* rp = reinterpret_cast<const float4*>(kb + (size_t)kbrow * DDIM);
        float acc = 0.f;
#pragma unroll
        for (int c = 0; c < 8; c++) {
            float4 v  = rp[lane + 32 * c];
            float4 qq = reinterpret_cast<float4*>(qrow)[lane + 32 * c];
            float dx = v.x - qq.x, dy = v.y - qq.y, dz = v.z - qq.z, dw = v.w - qq.w;
            acc += dx * dx + dy * dy + dz * dz + dw * dw;
        }
#pragma unroll
        for (int o = 16; o; o >>= 1) acc += __shfl_xor_sync(0xffffffffu, acc, o);
        if (lane == 0) { ed[k] = acc; ei[k] = kbrow; }
    }
    __syncthreads();

    // exact top-32 of the 64 rescored candidates
    if (tid < RESCORE) {
        float mine = ed[tid];
        int r = 0;
#pragma unroll 8
        for (int j = 0; j < RESCORE; j++) {
            float v = ed[j];
            r += (v < mine) || (v == mine && j < tid);
        }
        if (r < TOPK) { sd[r] = mine; si[r] = ei[tid]; }
    }
    __syncthreads();

    // softmax(-sqrt(d2)/temp) over exact distances
    if (wid == 0) {
        float dist  = sqrtf(fmaxf(sd[lane], 0.0f));
        float logit = -dist / temp_p[0];
        float m = logit;
#pragma unroll
        for (int o = 16; o; o >>= 1) m = fmaxf(m, __shfl_xor_sync(0xffffffffu, m, o));
        float e = expf(logit - m);
        float ss = e;
#pragma unroll
        for (int o = 16; o; o >>= 1) ss += __shfl_xor_sync(0xffffffffu, ss, o);
        wts[lane] = e / ss;
    }
    __syncthreads();

    // T = sum_k w_k * kb[idx_k] (rows are L2-hot from rescoring pass)
    float4 acc = make_float4(0.f, 0.f, 0.f, 0.f);
#pragma unroll 4
    for (int k = 0; k < TOPK; k++) {
        float wk = wts[k];
        float4 v = reinterpret_cast<const float4*>(kb + (size_t)si[k] * DDIM)[tid];
        acc.x += wk * v.x; acc.y += wk * v.y; acc.z += wk * v.z; acc.w += wk * v.w;
    }

    float4* o4 = reinterpret_cast<float4*>(out + (size_t)q * OUTW);
    float4 cv = reinterpret_cast<const float4*>(Cm + (size_t)q * DDIM)[tid];
    float4 kv = reinterpret_cast<const float4*>(Km + (size_t)q * DDIM)[tid];
    float4 rr;
    rr.x = silu_f(cv.x); rr.y = silu_f(cv.y); rr.z = silu_f(cv.z); rr.w = silu_f(cv.w);
    o4[tid] = rr;
    rr.x = silu_f(0.5f * kv.x); rr.y = silu_f(0.5f * kv.y);
    rr.z = silu_f(0.5f * kv.z); rr.w = silu_f(0.5f * kv.w);
    o4[256 + tid] = rr;
    rr.x = silu_f(0.25f * acc.x); rr.y = silu_f(0.25f * acc.y);
    rr.z = silu_f(0.25f * acc.z); rr.w = silu_f(0.25f * acc.w);
    o4[512 + tid] = rr;
}

// ---------------- launch ------------------------------------------------------
extern "C" void kernel_launch(void* const* d_in, const int* in_sizes, int n_in,
                              void* d_out, int out_size) {
    int iC = -1, iK = -1, iKB = -1, iQ = -1, iT = -1;
    for (int i = 0; i < n_in; i++) {
        int s = in_sizes[i];
        if (s == NKB * DDIM)        iKB = i;
        else if (s == DDIM * DDIM)  iQ = i;
        else if (s == BATCH * DDIM) { if (iC < 0) iC = i; else iK = i; }
        else if (s == 1)            { if (iT < 0) iT = i; }
    }
    const float* C    = (const float*)d_in[iC];
    const float* Kin  = (const float*)d_in[iK];
    const float* kb   = (const float*)d_in[iKB];
    const float* Qw   = (const float*)d_in[iQ];
    const float* temp = (const float*)d_in[iT];
    float* out = (float*)d_out;

    cudaFuncSetAttribute(dist_topk_cp, cudaFuncAttributeMaxDynamicSharedMemorySize, K3_SMEM);

    qgemm_fp32<<<dim3(DDIM / 128, BATCH / 128), 256>>>(C, Qw);
    rowsq_kernel<<<NKB / 8, 256>>>(kb);
    dist_topk_cp<<<dim3(BATCH / 128, NSPLIT), 256, K3_SMEM>>>(kb);
    finalize_kernel<<<BATCH, 256>>>(kb, C, Kin, temp, out);
}

// round 8
// speedup vs baseline: 2.0178x; 1.8461x over previous
#include <cuda_runtime.h>
#include <cuda_bf16.h>
#include <mma.h>
#include <math.h>
#include <stdint.h>

using namespace nvcuda;

#define BATCH   4096
#define DDIM    1024
#define NKB     65536
#define NSPLIT  4
#define KBSPLIT (NKB / NSPLIT)      // 16384
#define TOPK    32
#define OUTW    3072
#define TILE_N  128
#define TILES   (KBSPLIT / TILE_N)  // 128 tiles per CTA
#define KCHUNK  64                  // K elems per pipeline stage
#define SPT     (DDIM / KCHUNK)     // 16 chunks per tile
#define NCHUNK  (TILES * SPT)       // 2048
#define NLIST   (NSPLIT * 2)        // 8 partial top-k lists per query
#define NCAND   (NLIST * TOPK)      // 256 candidates per query
#define RESCORE 64                  // exact-rescore margin

// ---- K3 shared memory layout (bytes) ----
// stage: A 128 x 72 bf16 (18432 B) + B 128 x 72 bf16 (18432 B) = 36864 B
#define STG_BYTES 36864
#define OFF_D     73728             // Ds 128x132 fp32 (67584 B)
#define OFF_KQ    141312            // 128 kb_sq (512 B)
#define K3_SMEM   141824

// ---------------- scratch (static device globals) ----------------
__device__ float          g_q[BATCH * DDIM];     // exact fp32 q (for rescoring)
__device__ __nv_bfloat16  g_qh[BATCH * DDIM];    // bf16 q (for MMA)
__device__ __nv_bfloat16  g_kbh[NKB * DDIM];     // bf16 kb (for MMA)
__device__ float          g_kbsq[NKB];
__device__ float          g_pd[BATCH * NCAND];
__device__ int            g_pi[BATCH * NCAND];

__device__ __forceinline__ float f_inf() { return __int_as_float(0x7f800000); }

__device__ __forceinline__ uint32_t smem_u32(const void* p) {
    uint32_t a;
    asm("{ .reg .u64 t; cvta.to.shared.u64 t, %1; cvt.u32.u64 %0, t; }" : "=r"(a) : "l"(p));
    return a;
}
__device__ __forceinline__ void cp16(uint32_t dst, const void* src) {
    asm volatile("cp.async.cg.shared.global [%0], [%1], 16;" :: "r"(dst), "l"(src));
}
#define CP_COMMIT() asm volatile("cp.async.commit_group;" ::: "memory")
#define CP_WAIT0()  asm volatile("cp.async.wait_group 0;"  ::: "memory")

__device__ __forceinline__ uint2 f4_to_bf8(float4 v) {
    __nv_bfloat162 lo = __floats2bfloat162_rn(v.x, v.y);
    __nv_bfloat162 hi = __floats2bfloat162_rn(v.z, v.w);
    uint2 r;
    r.x = *reinterpret_cast<uint32_t*>(&lo);
    r.y = *reinterpret_cast<uint32_t*>(&hi);
    return r;
}

// ---------------- K1: q = C @ Q^T, exact fp32 SIMT; also emits bf16 q -------
__global__ __launch_bounds__(256) void qgemm_fp32(const float* __restrict__ Cm,
                                                  const float* __restrict__ Qw) {
    __shared__ float At[8][132];   // transposed: At[k][m]
    __shared__ float Bt[8][132];   // transposed: Bt[k][n]
    const int tid = threadIdx.x;
    const int mbase = blockIdx.y * 128, nbase = blockIdx.x * 128;
    const int tr = tid >> 4, tc = tid & 15;     // 16x16 thread grid, 8x8 micro-tile
    const int lr = tid >> 1, lc = (tid & 1) * 4;

    float acc[8][8];
#pragma unroll
    for (int i = 0; i < 8; i++)
#pragma unroll
        for (int j = 0; j < 8; j++) acc[i][j] = 0.f;

    for (int kk = 0; kk < DDIM; kk += 8) {
        float4 av = *reinterpret_cast<const float4*>(Cm + (size_t)(mbase + lr) * DDIM + kk + lc);
        float4 bv = *reinterpret_cast<const float4*>(Qw + (size_t)(nbase + lr) * DDIM + kk + lc);
        __syncthreads();
        At[lc + 0][lr] = av.x; At[lc + 1][lr] = av.y; At[lc + 2][lr] = av.z; At[lc + 3][lr] = av.w;
        Bt[lc + 0][lr] = bv.x; Bt[lc + 1][lr] = bv.y; Bt[lc + 2][lr] = bv.z; Bt[lc + 3][lr] = bv.w;
        __syncthreads();
#pragma unroll
        for (int k = 0; k < 8; k++) {
            float4 a0 = *reinterpret_cast<float4*>(&At[k][tr * 8]);
            float4 a1 = *reinterpret_cast<float4*>(&At[k][tr * 8 + 4]);
            float4 b0 = *reinterpret_cast<float4*>(&Bt[k][tc * 8]);
            float4 b1 = *reinterpret_cast<float4*>(&Bt[k][tc * 8 + 4]);
            float a[8] = {a0.x, a0.y, a0.z, a0.w, a1.x, a1.y, a1.z, a1.w};
            float b[8] = {b0.x, b0.y, b0.z, b0.w, b1.x, b1.y, b1.z, b1.w};
#pragma unroll
            for (int i = 0; i < 8; i++)
#pragma unroll
                for (int j = 0; j < 8; j++) acc[i][j] += a[i] * b[j];
        }
    }
#pragma unroll
    for (int i = 0; i < 8; i++) {
        const size_t rowoff = (size_t)(mbase + tr * 8 + i) * DDIM + nbase + tc * 8;
#pragma unroll
        for (int j = 0; j < 8; j += 4) {
            float4 v = make_float4(acc[i][j], acc[i][j + 1], acc[i][j + 2], acc[i][j + 3]);
            *reinterpret_cast<float4*>(g_q + rowoff + j) = v;
            *reinterpret_cast<uint2*>(g_qh + rowoff + j) = f4_to_bf8(v);
        }
    }
}

// ---------------- K2: kb -> bf16 + row sums of squares (fused) --------------
__global__ __launch_bounds__(256) void kbprep_kernel(const float* __restrict__ kb) {
    int warp = threadIdx.x >> 5, lane = threadIdx.x & 31;
    int row = blockIdx.x * 8 + warp;
    if (row >= NKB) return;
    const float4* p = reinterpret_cast<const float4*>(kb + (size_t)row * DDIM);
    __nv_bfloat16* dst = g_kbh + (size_t)row * DDIM;
    float s = 0.f;
#pragma unroll
    for (int i = 0; i < 8; i++) {
        float4 v = p[lane + i * 32];
        s += v.x * v.x + v.y * v.y + v.z * v.z + v.w * v.w;
        *reinterpret_cast<uint2*>(dst + (lane + i * 32) * 4) = f4_to_bf8(v);
    }
#pragma unroll
    for (int o = 16; o; o >>= 1) s += __shfl_xor_sync(0xffffffffu, s, o);
    if (lane == 0) g_kbsq[row] = s;
}

// ---------------- K3: cp.async pipelined bf16 MMA + streaming top-32 --------
__device__ __forceinline__ void k3_issue(uint32_t sb, int tid, int mbase, int split, int g) {
    const int t = g >> 4, s = g & 15, stage = g & 1;
    const int kk = s * KCHUNK;
    const int nbase = split * KBSPLIT + t * TILE_N;
    const uint32_t sA = sb + stage * STG_BYTES;
    const uint32_t sB = sA + 18432;
    // A: 128 rows x 64 bf16 = 128 B/row = 8 x 16B chunks; 1024 slots, 4/thread
#pragma unroll
    for (int i = 0; i < 4; i++) {
        int e = tid + i * 256, r = e >> 3, c = e & 7;
        cp16(sA + (uint32_t)(r * 144 + c * 16),
             g_qh + (size_t)(mbase + r) * DDIM + kk + c * 8);
    }
#pragma unroll
    for (int i = 0; i < 4; i++) {
        int e = tid + i * 256, r = e >> 3, c = e & 7;
        cp16(sB + (uint32_t)(r * 144 + c * 16),
             g_kbh + (size_t)(nbase + r) * DDIM + kk + c * 8);
    }
    CP_COMMIT();
}

__global__ __launch_bounds__(256, 1) void dist_topk_cp() {
    extern __shared__ char smem[];
    const uint32_t sb = smem_u32(smem);
    float* Ds     = reinterpret_cast<float*>(smem + OFF_D);
    float* s_kbsq = reinterpret_cast<float*>(smem + OFF_KQ);
    const int tid  = threadIdx.x;
    const int warp = tid >> 5, wm = warp >> 1, wn = warp & 1;
    const int mbase = blockIdx.x * 128;
    const int split = blockIdx.y;
    const int row = tid & 127, half = tid >> 7;

    float td[TOPK];
    int   ti[TOPK];
#pragma unroll
    for (int k = 0; k < TOPK; k++) { td[k] = f_inf(); ti[k] = 0; }
    float rmax = f_inf();
    int   rpos = 0;

    wmma::fragment<wmma::accumulator, 16, 16, 16, float> fc[2][4];
#pragma unroll
    for (int i = 0; i < 2; i++)
#pragma unroll
        for (int j = 0; j < 4; j++) wmma::fill_fragment(fc[i][j], 0.0f);

    k3_issue(sb, tid, mbase, split, 0);

    for (int g = 0; g < NCHUNK; g++) {
        CP_WAIT0();
        __syncthreads();
        if (g + 1 < NCHUNK) k3_issue(sb, tid, mbase, split, g + 1);

        {
            const __nv_bfloat16* As =
                reinterpret_cast<const __nv_bfloat16*>(smem + (g & 1) * STG_BYTES);
            const __nv_bfloat16* Bs = As + 9216;   // +18432 bytes
#pragma unroll
            for (int ks = 0; ks < 4; ks++) {
                wmma::fragment<wmma::matrix_a, 16, 16, 16, __nv_bfloat16, wmma::row_major> fa0, fa1;
                wmma::load_matrix_sync(fa0, As + (wm * 32) * 72 + ks * 16, 72);
                wmma::load_matrix_sync(fa1, As + (wm * 32 + 16) * 72 + ks * 16, 72);
#pragma unroll
                for (int j = 0; j < 4; j++) {
                    wmma::fragment<wmma::matrix_b, 16, 16, 16, __nv_bfloat16, wmma::col_major> fb;
                    wmma::load_matrix_sync(fb, Bs + (wn * 64 + j * 16) * 72 + ks * 16, 72);
                    wmma::mma_sync(fc[0][j], fa0, fb, fc[0][j]);
                    wmma::mma_sync(fc[1][j], fa1, fb, fc[1][j]);
                }
            }
        }

        if ((g & (SPT - 1)) == SPT - 1) {
            const int t = g >> 4;
            const int nbase = split * KBSPLIT + t * TILE_N;
#pragma unroll
            for (int i = 0; i < 2; i++)
#pragma unroll
                for (int j = 0; j < 4; j++)
                    wmma::store_matrix_sync(Ds + (wm * 32 + i * 16) * 132 + wn * 64 + j * 16,
                                            fc[i][j], 132, wmma::mem_row_major);
            if (tid < 128) s_kbsq[tid] = g_kbsq[nbase + tid];
            __syncthreads();

            const float* drow = Ds + row * 132 + half * 64;
            const float* kq   = s_kbsq + half * 64;
            const int ibase   = nbase + half * 64;
#pragma unroll 4
            for (int j = 0; j < 64; j++) {
                float sc = kq[j] - 2.0f * drow[j];
                if (sc < rmax) {
                    int idx = ibase + j;
#pragma unroll
                    for (int k = 0; k < TOPK; k++)
                        if (k == rpos) { td[k] = sc; ti[k] = idx; }
                    float nm = -3.4e38f;
                    int np = 0;
#pragma unroll
                    for (int k = 0; k < TOPK; k++)
                        if (td[k] > nm) { nm = td[k]; np = k; }
                    rmax = nm; rpos = np;
                }
            }
            __syncthreads();
#pragma unroll
            for (int i = 0; i < 2; i++)
#pragma unroll
                for (int j = 0; j < 4; j++) wmma::fill_fragment(fc[i][j], 0.0f);
        }
    }

    const int list = split * 2 + half;
#pragma unroll
    for (int k = 0; k < TOPK; k++) {
        size_t o = ((size_t)(mbase + row) * NLIST + list) * TOPK + k;
        g_pd[o] = td[k];
        g_pi[o] = ti[k];
    }
}

// ---------------- K4: approx top-64 -> exact rescoring -> top-32 -> SiLU ----
__device__ __forceinline__ float silu_f(float x) { return x / (1.0f + expf(-x)); }

__global__ __launch_bounds__(256) void finalize_kernel(const float* __restrict__ kb,
                                                       const float* __restrict__ Cm,
                                                       const float* __restrict__ Km,
                                                       const float* __restrict__ temp_p,
                                                       float* __restrict__ out) {
    __shared__ float qrow[DDIM];
    __shared__ float cd[NCAND];
    __shared__ int   ci[NCAND];
    __shared__ int   slot64[RESCORE];
    __shared__ float ed[RESCORE];
    __shared__ int   ei[RESCORE];
    __shared__ float sd[TOPK];
    __shared__ int   si[TOPK];
    __shared__ float wts[TOPK];

    const int q = blockIdx.x, tid = threadIdx.x, wid = tid >> 5, lane = tid & 31;

    cd[tid] = g_pd[(size_t)q * NCAND + tid];
    ci[tid] = g_pi[(size_t)q * NCAND + tid];
    reinterpret_cast<float4*>(qrow)[tid] =
        reinterpret_cast<const float4*>(g_q + (size_t)q * DDIM)[tid];
    __syncthreads();

    // rank each candidate among the 256 approx scores (index tiebreak)
    {
        float mine = cd[tid];
        int r = 0;
#pragma unroll 8
        for (int j = 0; j < NCAND; j++) {
            float v = cd[j];
            r += (v < mine) || (v == mine && j < tid);
        }
        if (r < RESCORE) slot64[r] = tid;
    }
    __syncthreads();

    // exact fp32 d2 for the top-64 approx candidates (warp w: 8 rows)
#pragma unroll 1
    for (int r8 = 0; r8 < RESCORE / 8; r8++) {
        const int k = wid * (RESCORE / 8) + r8;
        const int kbrow = ci[slot64[k]];
        const float4* rp = reinterpret_cast<const float4*>(kb + (size_t)kbrow * DDIM);
        float acc = 0.f;
#pragma unroll
        for (int c = 0; c < 8; c++) {
            float4 v  = rp[lane + 32 * c];
            float4 qq = reinterpret_cast<float4*>(qrow)[lane + 32 * c];
            float dx = v.x - qq.x, dy = v.y - qq.y, dz = v.z - qq.z, dw = v.w - qq.w;
            acc += dx * dx + dy * dy + dz * dz + dw * dw;
        }
#pragma unroll
        for (int o = 16; o; o >>= 1) acc += __shfl_xor_sync(0xffffffffu, acc, o);
        if (lane == 0) { ed[k] = acc; ei[k] = kbrow; }
    }
    __syncthreads();

    // exact top-32 of the 64 rescored candidates
    if (tid < RESCORE) {
        float mine = ed[tid];
        int r = 0;
#pragma unroll 8
        for (int j = 0; j < RESCORE; j++) {
            float v = ed[j];
            r += (v < mine) || (v == mine && j < tid);
        }
        if (r < TOPK) { sd[r] = mine; si[r] = ei[tid]; }
    }
    __syncthreads();

    // softmax(-sqrt(d2)/temp) over exact distances
    if (wid == 0) {
        float dist  = sqrtf(fmaxf(sd[lane], 0.0f));
        float logit = -dist / temp_p[0];
        float m = logit;
#pragma unroll
        for (int o = 16; o; o >>= 1) m = fmaxf(m, __shfl_xor_sync(0xffffffffu, m, o));
        float e = expf(logit - m);
        float ss = e;
#pragma unroll
        for (int o = 16; o; o >>= 1) ss += __shfl_xor_sync(0xffffffffu, ss, o);
        wts[lane] = e / ss;
    }
    __syncthreads();

    // T = sum_k w_k * kb[idx_k] (rows are L2-hot from rescoring pass)
    float4 acc = make_float4(0.f, 0.f, 0.f, 0.f);
#pragma unroll 4
    for (int k = 0; k < TOPK; k++) {
        float wk = wts[k];
        float4 v = reinterpret_cast<const float4*>(kb + (size_t)si[k] * DDIM)[tid];
        acc.x += wk * v.x; acc.y += wk * v.y; acc.z += wk * v.z; acc.w += wk * v.w;
    }

    float4* o4 = reinterpret_cast<float4*>(out + (size_t)q * OUTW);
    float4 cv = reinterpret_cast<const float4*>(Cm + (size_t)q * DDIM)[tid];
    float4 kv = reinterpret_cast<const float4*>(Km + (size_t)q * DDIM)[tid];
    float4 rr;
    rr.x = silu_f(cv.x); rr.y = silu_f(cv.y); rr.z = silu_f(cv.z); rr.w = silu_f(cv.w);
    o4[tid] = rr;
    rr.x = silu_f(0.5f * kv.x); rr.y = silu_f(0.5f * kv.y);
    rr.z = silu_f(0.5f * kv.z); rr.w = silu_f(0.5f * kv.w);
    o4[256 + tid] = rr;
    rr.x = silu_f(0.25f * acc.x); rr.y = silu_f(0.25f * acc.y);
    rr.z = silu_f(0.25f * acc.z); rr.w = silu_f(0.25f * acc.w);
    o4[512 + tid] = rr;
}

// ---------------- launch ------------------------------------------------------
extern "C" void kernel_launch(void* const* d_in, const int* in_sizes, int n_in,
                              void* d_out, int out_size) {
    int iC = -1, iK = -1, iKB = -1, iQ = -1, iT = -1;
    for (int i = 0; i < n_in; i++) {
        int s = in_sizes[i];
        if (s == NKB * DDIM)        iKB = i;
        else if (s == DDIM * DDIM)  iQ = i;
        else if (s == BATCH * DDIM) { if (iC < 0) iC = i; else iK = i; }
        else if (s == 1)            { if (iT < 0) iT = i; }
    }
    const float* C    = (const float*)d_in[iC];
    const float* Kin  = (const float*)d_in[iK];
    const float* kb   = (const float*)d_in[iKB];
    const float* Qw   = (const float*)d_in[iQ];
    const float* temp = (const float*)d_in[iT];
    float* out = (float*)d_out;

    cudaFuncSetAttribute(dist_topk_cp, cudaFuncAttributeMaxDynamicSharedMemorySize, K3_SMEM);

    qgemm_fp32<<<dim3(DDIM / 128, BATCH / 128), 256>>>(C, Qw);
    kbprep_kernel<<<NKB / 8, 256>>>(kb);
    dist_topk_cp<<<dim3(BATCH / 128, NSPLIT), 256, K3_SMEM>>>();
    finalize_kernel<<<BATCH, 256>>>(kb, C, Kin, temp, out);
}